// round 13
// baseline (speedup 1.0000x reference)
#include <cuda_runtime.h>
#include <cstdint>

#define BATCH   8
#define CH      256
#define HH      80
#define WW      80
#define HW      (HH*WW)          // 6400
#define OC      32
#define GROUPS  4
#define OH      160
#define OW      160
#define OHW     (OH*OW)          // 25600

#define SC      16               // channels per conv stage
#define NSTAGE  (CH/SC)          // 16

typedef unsigned long long ull;

// scratch for conv output: 8*32*6400 floats = 6.55 MB
__device__ float g_off[BATCH * OC * HW];

__device__ __forceinline__ ull pack2(float a, float b) {
    ull r;
    asm("mov.b64 %0, {%1, %2};" : "=l"(r) : "f"(a), "f"(b));
    return r;
}

__device__ __forceinline__ ull ffma2(ull a, ull b, ull c) {
    ull d;
    asm("fma.rn.f32x2 %0, %1, %2, %3;" : "=l"(d) : "l"(a), "l"(b), "l"(c));
    return d;
}

// ---------------------------------------------------------------------------
// Kernel 1 (v6 — proven ~31us, untouched): 1x1 conv, smem-staged x.
// ---------------------------------------------------------------------------
__global__ void __launch_bounds__(256)
conv_off_kernel(const float* __restrict__ x,
                const float* __restrict__ wq,
                const float* __restrict__ bias) {
    __shared__ float  ws[CH * OC];          // [c][o], 32 KB
    __shared__ float4 xs[2][SC][32];        // 2 x 8 KB

    int tid = threadIdx.x;
    for (int idx = tid; idx < CH * OC; idx += 256) {
        int o = idx >> 8;                   // coalesced over c
        int c = idx & 255;
        ws[c * OC + o] = __ldg(&wq[o * CH + c]);
    }

    int b   = blockIdx.x / 50;              // 400 blocks = 8 b x 50
    int qq0 = (blockIdx.x % 50) * 32;       // float4 base within channel
    const float4* xb = reinterpret_cast<const float4*>(x + (size_t)b * CH * HW);

    int c_l0 = tid >> 5;                    // 0..7
    int q0   = tid & 31;

    float4 r0 = __ldg(&xb[(size_t)(c_l0)     * (HW / 4) + qq0 + q0]);
    float4 r1 = __ldg(&xb[(size_t)(c_l0 + 8) * (HW / 4) + qq0 + q0]);
    xs[0][c_l0][q0]     = r0;
    xs[0][c_l0 + 8][q0] = r1;
    __syncthreads();

    int lane = tid & 31;
    int og   = tid >> 5;                    // 4 oc per warp
    const float* wso = ws + og * 4;

    ull accL[4], accH[4];
#pragma unroll
    for (int o = 0; o < 4; o++) { accL[o] = 0ULL; accH[o] = 0ULL; }

#pragma unroll 1
    for (int st = 0; st < NSTAGE; st++) {
        int cb  = st * SC;
        int buf = st & 1;

        if (st + 1 < NSTAGE) {
            r0 = __ldg(&xb[(size_t)(cb + SC + c_l0)     * (HW / 4) + qq0 + q0]);
            r1 = __ldg(&xb[(size_t)(cb + SC + c_l0 + 8) * (HW / 4) + qq0 + q0]);
        }

#pragma unroll
        for (int cl = 0; cl < SC; cl++) {
            float4 xv = xs[buf][cl][lane];
            ull lo = pack2(xv.x, xv.y);
            ull hi = pack2(xv.z, xv.w);
            float4 w4 = *reinterpret_cast<const float4*>(wso + (cb + cl) * OC);
            ull pw0 = pack2(w4.x, w4.x);
            ull pw1 = pack2(w4.y, w4.y);
            ull pw2 = pack2(w4.z, w4.z);
            ull pw3 = pack2(w4.w, w4.w);
            accL[0] = ffma2(lo, pw0, accL[0]);
            accH[0] = ffma2(hi, pw0, accH[0]);
            accL[1] = ffma2(lo, pw1, accL[1]);
            accH[1] = ffma2(hi, pw1, accH[1]);
            accL[2] = ffma2(lo, pw2, accL[2]);
            accH[2] = ffma2(hi, pw2, accH[2]);
            accL[3] = ffma2(lo, pw3, accL[3]);
            accH[3] = ffma2(hi, pw3, accH[3]);
        }

        __syncthreads();
        if (st + 1 < NSTAGE) {
            xs[buf ^ 1][c_l0][q0]     = r0;
            xs[buf ^ 1][c_l0 + 8][q0] = r1;
            __syncthreads();
        }
    }

    float4* offp = reinterpret_cast<float4*>(g_off + (size_t)b * OC * HW);
#pragma unroll
    for (int o = 0; o < 4; o++) {
        int oc = og * 4 + o;
        float bo = __ldg(&bias[oc]);
        float4 v;
        v.x = __uint_as_float((unsigned)(accL[o] & 0xffffffffULL)) + bo;
        v.y = __uint_as_float((unsigned)(accL[o] >> 32)) + bo;
        v.z = __uint_as_float((unsigned)(accH[o] & 0xffffffffULL)) + bo;
        v.w = __uint_as_float((unsigned)(accH[o] >> 32)) + bo;
        offp[(size_t)oc * (HW / 4) + qq0 + lane] = v;
    }
}

// ---------------------------------------------------------------------------
// Kernel 2 (v9): tiled bilinear sampling, occupancy push.
// launch_bounds(128,8) -> <=64 regs, 32 warps/SM (was 21). Weights (wx,wy)
// pairs in smem float4 (8 LDS.128/ch). Incremental pointers in the channel
// loop to trim registers.
// ---------------------------------------------------------------------------
__device__ __noinline__ void sample_fallback(
    const float* __restrict__ offb, const float* __restrict__ bp,
    float* __restrict__ opb, int gi, int hbase, int wbase, int ohb, int owb)
{
    for (int c = 0; c < 16; c++) {
        const float* pc = bp + (size_t)c * HW;
        float* oc = opb + (size_t)c * OHW;
        for (int r = 0; r < 4; r++) {
            float vv[4];
            for (int s = 0; s < 4; s++) {
                int hprime = hbase + (r >> 1);
                int i = r & 1;
                int wprime = wbase + (s >> 1);
                int j = s & 1;
                int k = gi * 4 + i * 2 + j;
                const float* op2 = offb + hprime * WW + wprime;
                float offx = __ldg(op2 + (size_t)k * HW);
                float offy = __ldg(op2 + (size_t)(16 + k) * HW);
                float px = (float)wprime + 0.25f * (offx + (float)(2 * j - 1));
                float py = (float)hprime + 0.25f * (offy + (float)(2 * i - 1));
                float ix = fminf(fmaxf(px, 0.0f), (float)(WW - 1));
                float iy = fminf(fmaxf(py, 0.0f), (float)(HH - 1));
                float fx = floorf(ix), fy = floorf(iy);
                int x0 = (int)fx, y0 = (int)fy;
                float wx = ix - fx, wy = iy - fy;
                int x1 = min(x0 + 1, WW - 1);
                int y1 = min(y0 + 1, HH - 1);
                float a0 = __ldg(pc + y0 * WW + x0);
                float a1 = __ldg(pc + y0 * WW + x1);
                float a2 = __ldg(pc + y1 * WW + x0);
                float a3 = __ldg(pc + y1 * WW + x1);
                float h0 = fmaf(wx, a1 - a0, a0);
                float h1 = fmaf(wx, a3 - a2, a2);
                vv[s] = fmaf(wy, h1 - h0, h0);
            }
            float4 v4 = make_float4(vv[0], vv[1], vv[2], vv[3]);
            *reinterpret_cast<float4*>(oc + (size_t)(ohb + r) * OW + owb) = v4;
        }
    }
}

__global__ void __launch_bounds__(128, 8)
sample_kernel(const float* __restrict__ x, float* __restrict__ out) {
    // [r*2 + s/2][tid] = (wx_s, wy_s, wx_{s+1}, wy_{s+1}); 16 KB
    __shared__ float4 sw4[8][128];

    int tid = threadIdx.x;
    int t = blockIdx.x * 128 + tid;      // 204800 threads
    int wp = t % 40;  int u = t / 40;
    int hp = u % 40;  u /= 40;
    int cchunk = u & 3;  u >>= 2;
    int gi = u & 3;
    int b  = u >> 2;

    int hbase = 2 * hp, wbase = 2 * wp;

    const float* offb = g_off + (size_t)b * OC * HW;

    bool valid = true;
#pragma unroll
    for (int r = 0; r < 4; r++) {
        int hprime = hbase + (r >> 1);
        int i = r & 1;
#pragma unroll
        for (int s = 0; s < 4; s++) {
            int wprime = wbase + (s >> 1);
            int j = s & 1;
            int k = gi * 4 + i * 2 + j;
            const float* op2 = offb + hprime * WW + wprime;
            float offx = __ldg(op2 + (size_t)k * HW);
            float offy = __ldg(op2 + (size_t)(16 + k) * HW);
            float px = (float)wprime + 0.25f * (offx + (float)(2 * j - 1));
            float py = (float)hprime + 0.25f * (offy + (float)(2 * i - 1));
            float ix = fminf(fmaxf(px, 0.0f), (float)(WW - 1));
            float iy = fminf(fmaxf(py, 0.0f), (float)(HH - 1));
            int tx0 = (s >> 1) + (s & 1);
            int ty0 = (r >> 1) + (r & 1);
            float wx = ix - (float)(wbase - 1 + tx0);
            float wy = iy - (float)(hbase - 1 + ty0);
            reinterpret_cast<float2*>(&sw4[r * 2 + (s >> 1)][tid])[s & 1] =
                make_float2(wx, wy);
            valid = valid && (wx >= 0.0f) && (wx <= 1.0f)
                          && (wy >= 0.0f) && (wy <= 1.0f);
        }
    }

    int c0 = cchunk * 16;
    const float* bp = x + (size_t)(b * CH + gi * 64 + c0) * HW;
    int ohb = 4 * hp;
    int owb = 4 * wp;
    float* opb = out + (size_t)(b * CH + gi * 64 + c0) * OHW;

    if (!valid) {
        sample_fallback(offb, bp, opb, gi, hbase, wbase, ohb, owb);
        return;
    }

    int rowo[4];
#pragma unroll
    for (int tq = 0; tq < 4; tq++)
        rowo[tq] = min(max(hbase - 1 + tq, 0), HH - 1) * WW;
    int colL = max(wbase - 1, 0);
    int colR = min(wbase + 2, WW - 1);

    const float* pc = bp;
    float* oc = opb + (size_t)ohb * OW + owb;

#pragma unroll 1
    for (int c = 0; c < 16; c++) {
        float tv[16];
#pragma unroll
        for (int ty = 0; ty < 4; ty++) {
            const float* rowp = pc + rowo[ty];
            tv[ty * 4 + 0] = __ldg(rowp + colL);
            float2 mid = __ldg(reinterpret_cast<const float2*>(rowp + wbase));
            tv[ty * 4 + 1] = mid.x;
            tv[ty * 4 + 2] = mid.y;
            tv[ty * 4 + 3] = __ldg(rowp + colR);
        }

#pragma unroll
        for (int r = 0; r < 4; r++) {
            float4 wA = sw4[r * 2 + 0][tid];   // outputs s=0,1
            float4 wB = sw4[r * 2 + 1][tid];   // outputs s=2,3
            float vv[4];
#pragma unroll
            for (int sp = 0; sp < 2; sp++) {
                float4 wp4 = (sp == 0) ? wA : wB;
#pragma unroll
                for (int e = 0; e < 2; e++) {
                    int s = sp * 2 + e;
                    const int tx0 = (s >> 1) + (s & 1);
                    const int ty0 = (r >> 1) + (r & 1);
                    float wx = e ? wp4.z : wp4.x;
                    float wy = e ? wp4.w : wp4.y;
                    float a0 = tv[ty0 * 4 + tx0];
                    float a1 = tv[ty0 * 4 + tx0 + 1];
                    float a2 = tv[(ty0 + 1) * 4 + tx0];
                    float a3 = tv[(ty0 + 1) * 4 + tx0 + 1];
                    float h0 = fmaf(wx, a1 - a0, a0);
                    float h1 = fmaf(wx, a3 - a2, a2);
                    vv[s] = fmaf(wy, h1 - h0, h0);
                }
            }
            float4 v4 = make_float4(vv[0], vv[1], vv[2], vv[3]);
            *reinterpret_cast<float4*>(oc + (size_t)r * OW) = v4;
        }
        pc += HW;
        oc += OHW;
    }
}

extern "C" void kernel_launch(void* const* d_in, const int* in_sizes, int n_in,
                              void* d_out, int out_size) {
    const float* x    = (const float*)d_in[0];   // [8,256,80,80]
    const float* wq   = (const float*)d_in[1];   // [32,256,1,1]
    const float* bias = (const float*)d_in[2];   // [32]
    float* out = (float*)d_out;                  // [8,256,160,160]

    conv_off_kernel<<<400, 256>>>(x, wq, bias);
    sample_kernel<<<1600, 128>>>(x, out);
}

// round 14
// speedup vs baseline: 1.1016x; 1.1016x over previous
#include <cuda_runtime.h>
#include <cstdint>

#define BATCH   8
#define CH      256
#define HH      80
#define WW      80
#define HW      (HH*WW)          // 6400
#define OC      32
#define GROUPS  4
#define OH      160
#define OW      160
#define OHW     (OH*OW)          // 25600

#define SC      16               // channels per conv stage
#define NSTAGE  (CH/SC)          // 16

typedef unsigned long long ull;

// scratch for conv output: 8*32*6400 floats = 6.55 MB
__device__ float g_off[BATCH * OC * HW];

__device__ __forceinline__ ull pack2(float a, float b) {
    ull r;
    asm("mov.b64 %0, {%1, %2};" : "=l"(r) : "f"(a), "f"(b));
    return r;
}

__device__ __forceinline__ ull ffma2(ull a, ull b, ull c) {
    ull d;
    asm("fma.rn.f32x2 %0, %1, %2, %3;" : "=l"(d) : "l"(a), "l"(b), "l"(c));
    return d;
}

__device__ __forceinline__ float lo_f(ull v) { return __uint_as_float((unsigned)(v & 0xffffffffULL)); }
__device__ __forceinline__ float hi_f(ull v) { return __uint_as_float((unsigned)(v >> 32)); }

// ---------------------------------------------------------------------------
// Kernel 1 (v6.1): 1x1 conv, smem-staged x — v6 structure, oc-pair inner loop.
// Block = 256 thr = 8 warps sharing the SAME 32 float4 positions; warp og
// owns oc [4og,4og+4) as TWO oc-pairs. Weights [c][o] float in smem: one
// broadcast LDS.128 gives (w0,w1),(w2,w3) already packed for FFMA2 — zero
// weight packs. Per c-iter: 2 LDS.128 + 4 x-dup packs + 8 FFMA2 (14 slots,
// was 18). Everything else identical to proven v6.
// ---------------------------------------------------------------------------
__global__ void __launch_bounds__(256)
conv_off_kernel(const float* __restrict__ x,
                const float* __restrict__ wq,
                const float* __restrict__ bias) {
    __shared__ float  ws[CH * OC];          // [c][o], 32 KB
    __shared__ float4 xs[2][SC][32];        // 2 x 8 KB

    int tid = threadIdx.x;
    for (int idx = tid; idx < CH * OC; idx += 256) {
        int o = idx >> 8;                   // coalesced over c
        int c = idx & 255;
        ws[c * OC + o] = __ldg(&wq[o * CH + c]);
    }

    int b   = blockIdx.x / 50;              // 400 blocks = 8 b x 50
    int qq0 = (blockIdx.x % 50) * 32;       // float4 base within channel
    const float4* xb = reinterpret_cast<const float4*>(x + (size_t)b * CH * HW);

    int c_l0 = tid >> 5;                    // 0..7
    int q0   = tid & 31;

    // prologue: stage 0
    float4 r0 = __ldg(&xb[(size_t)(c_l0)     * (HW / 4) + qq0 + q0]);
    float4 r1 = __ldg(&xb[(size_t)(c_l0 + 8) * (HW / 4) + qq0 + q0]);
    xs[0][c_l0][q0]     = r0;
    xs[0][c_l0 + 8][q0] = r1;
    __syncthreads();                        // covers ws fill + stage 0

    int lane = tid & 31;
    int og   = tid >> 5;                    // 4 oc (2 oc-pairs) per warp
    const float* wso = ws + og * 4;         // 16B-aligned within each c row

    // acc[i][p] = packed (sum for oc 4og+2p, sum for oc 4og+2p+1) at position i
    ull acc[4][2];
#pragma unroll
    for (int i = 0; i < 4; i++) { acc[i][0] = 0ULL; acc[i][1] = 0ULL; }

#pragma unroll 1
    for (int st = 0; st < NSTAGE; st++) {
        int cb  = st * SC;
        int buf = st & 1;

        if (st + 1 < NSTAGE) {
            r0 = __ldg(&xb[(size_t)(cb + SC + c_l0)     * (HW / 4) + qq0 + q0]);
            r1 = __ldg(&xb[(size_t)(cb + SC + c_l0 + 8) * (HW / 4) + qq0 + q0]);
        }

#pragma unroll
        for (int cl = 0; cl < SC; cl++) {
            float4 xv = xs[buf][cl][lane];                       // LDS.128
            ulonglong2 wp = *reinterpret_cast<const ulonglong2*>(
                wso + (cb + cl) * OC);                           // bcast LDS.128
            ull px0 = pack2(xv.x, xv.x);
            ull px1 = pack2(xv.y, xv.y);
            ull px2 = pack2(xv.z, xv.z);
            ull px3 = pack2(xv.w, xv.w);
            acc[0][0] = ffma2(px0, wp.x, acc[0][0]);
            acc[0][1] = ffma2(px0, wp.y, acc[0][1]);
            acc[1][0] = ffma2(px1, wp.x, acc[1][0]);
            acc[1][1] = ffma2(px1, wp.y, acc[1][1]);
            acc[2][0] = ffma2(px2, wp.x, acc[2][0]);
            acc[2][1] = ffma2(px2, wp.y, acc[2][1]);
            acc[3][0] = ffma2(px3, wp.x, acc[3][0]);
            acc[3][1] = ffma2(px3, wp.y, acc[3][1]);
        }

        __syncthreads();
        if (st + 1 < NSTAGE) {
            xs[buf ^ 1][c_l0][q0]     = r0;
            xs[buf ^ 1][c_l0 + 8][q0] = r1;
            __syncthreads();
        }
    }

    float4* offp = reinterpret_cast<float4*>(g_off + (size_t)b * OC * HW);
#pragma unroll
    for (int p = 0; p < 2; p++) {
#pragma unroll
        for (int e = 0; e < 2; e++) {
            int oc = og * 4 + 2 * p + e;
            float bo = __ldg(&bias[oc]);
            float4 v;
            v.x = (e ? hi_f(acc[0][p]) : lo_f(acc[0][p])) + bo;
            v.y = (e ? hi_f(acc[1][p]) : lo_f(acc[1][p])) + bo;
            v.z = (e ? hi_f(acc[2][p]) : lo_f(acc[2][p])) + bo;
            v.w = (e ? hi_f(acc[3][p]) : lo_f(acc[3][p])) + bo;
            offp[(size_t)oc * (HW / 4) + qq0 + lane] = v;
        }
    }
}

// ---------------------------------------------------------------------------
// Kernel 2 (v8 — reverted verbatim, proven 49.7us): tiled bilinear sampling.
// ---------------------------------------------------------------------------
__device__ __noinline__ void sample_fallback(
    const float* __restrict__ offb, const float* __restrict__ bp,
    float* __restrict__ opb, int gi, int hbase, int wbase, int ohb, int owb)
{
    for (int c = 0; c < 16; c++) {
        const float* pc = bp + (size_t)c * HW;
        float* oc = opb + (size_t)c * OHW;
        for (int r = 0; r < 4; r++) {
            float vv[4];
            for (int s = 0; s < 4; s++) {
                int hprime = hbase + (r >> 1);
                int i = r & 1;
                int wprime = wbase + (s >> 1);
                int j = s & 1;
                int k = gi * 4 + i * 2 + j;
                const float* op2 = offb + hprime * WW + wprime;
                float offx = __ldg(op2 + (size_t)k * HW);
                float offy = __ldg(op2 + (size_t)(16 + k) * HW);
                float px = (float)wprime + 0.25f * (offx + (float)(2 * j - 1));
                float py = (float)hprime + 0.25f * (offy + (float)(2 * i - 1));
                float ix = fminf(fmaxf(px, 0.0f), (float)(WW - 1));
                float iy = fminf(fmaxf(py, 0.0f), (float)(HH - 1));
                float fx = floorf(ix), fy = floorf(iy);
                int x0 = (int)fx, y0 = (int)fy;
                float wx = ix - fx, wy = iy - fy;
                int x1 = min(x0 + 1, WW - 1);
                int y1 = min(y0 + 1, HH - 1);
                float a0 = __ldg(pc + y0 * WW + x0);
                float a1 = __ldg(pc + y0 * WW + x1);
                float a2 = __ldg(pc + y1 * WW + x0);
                float a3 = __ldg(pc + y1 * WW + x1);
                float h0 = fmaf(wx, a1 - a0, a0);
                float h1 = fmaf(wx, a3 - a2, a2);
                vv[s] = fmaf(wy, h1 - h0, h0);
            }
            float4 v4 = make_float4(vv[0], vv[1], vv[2], vv[3]);
            *reinterpret_cast<float4*>(oc + (size_t)(ohb + r) * OW + owb) = v4;
        }
    }
}

__global__ void __launch_bounds__(128, 6)
sample_kernel(const float* __restrict__ x, float* __restrict__ out) {
    // [r*2 + s/2][tid] = (wx_s, wy_s, wx_{s+1}, wy_{s+1}); 16 KB
    __shared__ float4 sw4[8][128];

    int tid = threadIdx.x;
    int t = blockIdx.x * 128 + tid;      // 204800 threads
    int wp = t % 40;  int u = t / 40;
    int hp = u % 40;  u /= 40;
    int cchunk = u & 3;  u >>= 2;
    int gi = u & 3;
    int b  = u >> 2;

    int hbase = 2 * hp, wbase = 2 * wp;

    const float* offb = g_off + (size_t)b * OC * HW;

    bool valid = true;
#pragma unroll
    for (int r = 0; r < 4; r++) {
        int hprime = hbase + (r >> 1);
        int i = r & 1;
#pragma unroll
        for (int s = 0; s < 4; s++) {
            int wprime = wbase + (s >> 1);
            int j = s & 1;
            int k = gi * 4 + i * 2 + j;
            const float* op2 = offb + hprime * WW + wprime;
            float offx = __ldg(op2 + (size_t)k * HW);
            float offy = __ldg(op2 + (size_t)(16 + k) * HW);
            float px = (float)wprime + 0.25f * (offx + (float)(2 * j - 1));
            float py = (float)hprime + 0.25f * (offy + (float)(2 * i - 1));
            float ix = fminf(fmaxf(px, 0.0f), (float)(WW - 1));
            float iy = fminf(fmaxf(py, 0.0f), (float)(HH - 1));
            int tx0 = (s >> 1) + (s & 1);
            int ty0 = (r >> 1) + (r & 1);
            float wx = ix - (float)(wbase - 1 + tx0);
            float wy = iy - (float)(hbase - 1 + ty0);
            reinterpret_cast<float2*>(&sw4[r * 2 + (s >> 1)][tid])[s & 1] =
                make_float2(wx, wy);
            valid = valid && (wx >= 0.0f) && (wx <= 1.0f)
                          && (wy >= 0.0f) && (wy <= 1.0f);
        }
    }

    int c0 = cchunk * 16;
    const float* bp = x + (size_t)(b * CH + gi * 64 + c0) * HW;
    int ohb = 4 * hp;
    int owb = 4 * wp;
    float* opb = out + (size_t)(b * CH + gi * 64 + c0) * OHW;

    if (!valid) {
        sample_fallback(offb, bp, opb, gi, hbase, wbase, ohb, owb);
        return;
    }

    int rowo[4];
#pragma unroll
    for (int tq = 0; tq < 4; tq++)
        rowo[tq] = min(max(hbase - 1 + tq, 0), HH - 1) * WW;
    int colL = max(wbase - 1, 0);
    int colR = min(wbase + 2, WW - 1);

#pragma unroll 1
    for (int c = 0; c < 16; c++) {
        const float* pc = bp + (size_t)c * HW;
        float tv[16];
#pragma unroll
        for (int ty = 0; ty < 4; ty++) {
            const float* rowp = pc + rowo[ty];
            tv[ty * 4 + 0] = __ldg(rowp + colL);
            float2 mid = __ldg(reinterpret_cast<const float2*>(rowp + wbase));
            tv[ty * 4 + 1] = mid.x;
            tv[ty * 4 + 2] = mid.y;
            tv[ty * 4 + 3] = __ldg(rowp + colR);
        }

        float* oc = opb + (size_t)c * OHW;
#pragma unroll
        for (int r = 0; r < 4; r++) {
            float4 wA = sw4[r * 2 + 0][tid];   // outputs s=0,1
            float4 wB = sw4[r * 2 + 1][tid];   // outputs s=2,3
            float vv[4];
#pragma unroll
            for (int sp = 0; sp < 2; sp++) {
                float4 wp4 = (sp == 0) ? wA : wB;
#pragma unroll
                for (int e = 0; e < 2; e++) {
                    int s = sp * 2 + e;
                    const int tx0 = (s >> 1) + (s & 1);
                    const int ty0 = (r >> 1) + (r & 1);
                    float wx = e ? wp4.z : wp4.x;
                    float wy = e ? wp4.w : wp4.y;
                    float a0 = tv[ty0 * 4 + tx0];
                    float a1 = tv[ty0 * 4 + tx0 + 1];
                    float a2 = tv[(ty0 + 1) * 4 + tx0];
                    float a3 = tv[(ty0 + 1) * 4 + tx0 + 1];
                    float h0 = fmaf(wx, a1 - a0, a0);
                    float h1 = fmaf(wx, a3 - a2, a2);
                    vv[s] = fmaf(wy, h1 - h0, h0);
                }
            }
            float4 v4 = make_float4(vv[0], vv[1], vv[2], vv[3]);
            *reinterpret_cast<float4*>(oc + (size_t)(ohb + r) * OW + owb) = v4;
        }
    }
}

extern "C" void kernel_launch(void* const* d_in, const int* in_sizes, int n_in,
                              void* d_out, int out_size) {
    const float* x    = (const float*)d_in[0];   // [8,256,80,80]
    const float* wq   = (const float*)d_in[1];   // [32,256,1,1]
    const float* bias = (const float*)d_in[2];   // [32]
    float* out = (float*)d_out;                  // [8,256,160,160]

    conv_off_kernel<<<400, 256>>>(x, wq, bias);
    sample_kernel<<<1600, 128>>>(x, out);
}

// round 15
// speedup vs baseline: 1.1113x; 1.0088x over previous
#include <cuda_runtime.h>
#include <cstdint>

#define BATCH   8
#define CH      256
#define HH      80
#define WW      80
#define HW      (HH*WW)          // 6400
#define OC      32
#define GROUPS  4
#define OH      160
#define OW      160
#define OHW     (OH*OW)          // 25600

#define SC      32               // channels per conv stage
#define NSTAGE  (CH/SC)          // 8
#define CONV_SMEM (CH*OC*4 + 2*SC*32*16)   // 32KB ws + 32KB xs = 65536

typedef unsigned long long ull;

// scratch for conv output: 8*32*6400 floats = 6.55 MB
__device__ float g_off[BATCH * OC * HW];

__device__ __forceinline__ ull pack2(float a, float b) {
    ull r;
    asm("mov.b64 %0, {%1, %2};" : "=l"(r) : "f"(a), "f"(b));
    return r;
}

__device__ __forceinline__ ull ffma2(ull a, ull b, ull c) {
    ull d;
    asm("fma.rn.f32x2 %0, %1, %2, %3;" : "=l"(d) : "l"(a), "l"(b), "l"(c));
    return d;
}

__device__ __forceinline__ float lo_f(ull v) { return __uint_as_float((unsigned)(v & 0xffffffffULL)); }
__device__ __forceinline__ float hi_f(ull v) { return __uint_as_float((unsigned)(v >> 32)); }

// ---------------------------------------------------------------------------
// Kernel 1 (v6.2): 1x1 conv — v6.1 inner loop, SC=32 stages (8 stages, 16
// barriers instead of 32), 64KB dynamic smem (32KB weights + 2x16KB x bufs).
// Block = 256 thr = 8 warps sharing the SAME 32 float4 positions; warp og
// owns oc [4og,4og+4) as two oc-pairs (broadcast LDS.128 -> pre-packed w).
// ---------------------------------------------------------------------------
__global__ void __launch_bounds__(256)
conv_off_kernel(const float* __restrict__ x,
                const float* __restrict__ wq,
                const float* __restrict__ bias) {
    extern __shared__ float smdyn[];
    float*  ws = smdyn;                                   // [c][o], 32 KB
    float4* xs = reinterpret_cast<float4*>(smdyn + CH * OC);  // [2][SC][32]

    int tid = threadIdx.x;
    for (int idx = tid; idx < CH * OC; idx += 256) {
        int o = idx >> 8;                   // coalesced over c
        int c = idx & 255;
        ws[c * OC + o] = __ldg(&wq[o * CH + c]);
    }

    int b   = blockIdx.x / 50;              // 400 blocks = 8 b x 50
    int qq0 = (blockIdx.x % 50) * 32;       // float4 base within channel
    const float4* xb = reinterpret_cast<const float4*>(x + (size_t)b * CH * HW);

    int c_l0 = tid >> 5;                    // 0..7
    int q0   = tid & 31;

    // prologue: stage 0 (channels 0..31), 4 rows per thread
    float4 r[4];
#pragma unroll
    for (int k = 0; k < 4; k++)
        r[k] = __ldg(&xb[(size_t)(c_l0 + 8 * k) * (HW / 4) + qq0 + q0]);
#pragma unroll
    for (int k = 0; k < 4; k++)
        xs[(c_l0 + 8 * k) * 32 + q0] = r[k];
    __syncthreads();                        // covers ws fill + stage 0

    int lane = tid & 31;
    int og   = tid >> 5;                    // 4 oc (2 oc-pairs) per warp
    const float* wso = ws + og * 4;

    ull acc[4][2];
#pragma unroll
    for (int i = 0; i < 4; i++) { acc[i][0] = 0ULL; acc[i][1] = 0ULL; }

#pragma unroll 1
    for (int st = 0; st < NSTAGE; st++) {
        int cb  = st * SC;
        int buf = st & 1;

        if (st + 1 < NSTAGE) {
#pragma unroll
            for (int k = 0; k < 4; k++)
                r[k] = __ldg(&xb[(size_t)(cb + SC + c_l0 + 8 * k) * (HW / 4) + qq0 + q0]);
        }

        const float4* xsb = xs + buf * SC * 32;
#pragma unroll
        for (int cl = 0; cl < SC; cl++) {
            float4 xv = xsb[cl * 32 + lane];                     // LDS.128
            ulonglong2 wp = *reinterpret_cast<const ulonglong2*>(
                wso + (cb + cl) * OC);                           // bcast LDS.128
            ull px0 = pack2(xv.x, xv.x);
            ull px1 = pack2(xv.y, xv.y);
            ull px2 = pack2(xv.z, xv.z);
            ull px3 = pack2(xv.w, xv.w);
            acc[0][0] = ffma2(px0, wp.x, acc[0][0]);
            acc[0][1] = ffma2(px0, wp.y, acc[0][1]);
            acc[1][0] = ffma2(px1, wp.x, acc[1][0]);
            acc[1][1] = ffma2(px1, wp.y, acc[1][1]);
            acc[2][0] = ffma2(px2, wp.x, acc[2][0]);
            acc[2][1] = ffma2(px2, wp.y, acc[2][1]);
            acc[3][0] = ffma2(px3, wp.x, acc[3][0]);
            acc[3][1] = ffma2(px3, wp.y, acc[3][1]);
        }

        __syncthreads();                    // done reading buf
        if (st + 1 < NSTAGE) {
            float4* xsn = xs + (buf ^ 1) * SC * 32;
#pragma unroll
            for (int k = 0; k < 4; k++)
                xsn[(c_l0 + 8 * k) * 32 + q0] = r[k];
            __syncthreads();                // next buffer ready
        }
    }

    float4* offp = reinterpret_cast<float4*>(g_off + (size_t)b * OC * HW);
#pragma unroll
    for (int p = 0; p < 2; p++) {
#pragma unroll
        for (int e = 0; e < 2; e++) {
            int oc = og * 4 + 2 * p + e;
            float bo = __ldg(&bias[oc]);
            float4 v;
            v.x = (e ? hi_f(acc[0][p]) : lo_f(acc[0][p])) + bo;
            v.y = (e ? hi_f(acc[1][p]) : lo_f(acc[1][p])) + bo;
            v.z = (e ? hi_f(acc[2][p]) : lo_f(acc[2][p])) + bo;
            v.w = (e ? hi_f(acc[3][p]) : lo_f(acc[3][p])) + bo;
            offp[(size_t)oc * (HW / 4) + qq0 + lane] = v;
        }
    }
}

// ---------------------------------------------------------------------------
// Kernel 2 (v10): tiled bilinear sampling with explicit tap double-buffering.
// Channel c+1's 12 tap loads are issued before channel c's compute consumes
// its buffer -> sustained MLP ~24 (was 12). launch_bounds(128,5): <=102 regs,
// 20 warps/SM.
// ---------------------------------------------------------------------------
__device__ __forceinline__ void load_taps(float tv[16], const float* pc,
                                          const int rowo[4], int wbase,
                                          int colL, int colR) {
#pragma unroll
    for (int ty = 0; ty < 4; ty++) {
        const float* rowp = pc + rowo[ty];
        tv[ty * 4 + 0] = __ldg(rowp + colL);
        float2 mid = __ldg(reinterpret_cast<const float2*>(rowp + wbase));
        tv[ty * 4 + 1] = mid.x;
        tv[ty * 4 + 2] = mid.y;
        tv[ty * 4 + 3] = __ldg(rowp + colR);
    }
}

__device__ __forceinline__ void comp_store(const float tv[16],
                                           const float4 sw4[8][128], int tid,
                                           float* oc) {
#pragma unroll
    for (int r = 0; r < 4; r++) {
        float4 wA = sw4[r * 2 + 0][tid];
        float4 wB = sw4[r * 2 + 1][tid];
        float vv[4];
#pragma unroll
        for (int sp = 0; sp < 2; sp++) {
            float4 wp4 = (sp == 0) ? wA : wB;
#pragma unroll
            for (int e = 0; e < 2; e++) {
                int s = sp * 2 + e;
                const int tx0 = (s >> 1) + (s & 1);
                const int ty0 = (r >> 1) + (r & 1);
                float wx = e ? wp4.z : wp4.x;
                float wy = e ? wp4.w : wp4.y;
                float a0 = tv[ty0 * 4 + tx0];
                float a1 = tv[ty0 * 4 + tx0 + 1];
                float a2 = tv[(ty0 + 1) * 4 + tx0];
                float a3 = tv[(ty0 + 1) * 4 + tx0 + 1];
                float h0 = fmaf(wx, a1 - a0, a0);
                float h1 = fmaf(wx, a3 - a2, a2);
                vv[s] = fmaf(wy, h1 - h0, h0);
            }
        }
        *reinterpret_cast<float4*>(oc + (size_t)r * OW) =
            make_float4(vv[0], vv[1], vv[2], vv[3]);
    }
}

__device__ __noinline__ void sample_fallback(
    const float* __restrict__ offb, const float* __restrict__ bp,
    float* __restrict__ opb, int gi, int hbase, int wbase, int ohb, int owb)
{
    for (int c = 0; c < 16; c++) {
        const float* pc = bp + (size_t)c * HW;
        float* oc = opb + (size_t)c * OHW;
        for (int r = 0; r < 4; r++) {
            float vv[4];
            for (int s = 0; s < 4; s++) {
                int hprime = hbase + (r >> 1);
                int i = r & 1;
                int wprime = wbase + (s >> 1);
                int j = s & 1;
                int k = gi * 4 + i * 2 + j;
                const float* op2 = offb + hprime * WW + wprime;
                float offx = __ldg(op2 + (size_t)k * HW);
                float offy = __ldg(op2 + (size_t)(16 + k) * HW);
                float px = (float)wprime + 0.25f * (offx + (float)(2 * j - 1));
                float py = (float)hprime + 0.25f * (offy + (float)(2 * i - 1));
                float ix = fminf(fmaxf(px, 0.0f), (float)(WW - 1));
                float iy = fminf(fmaxf(py, 0.0f), (float)(HH - 1));
                float fx = floorf(ix), fy = floorf(iy);
                int x0 = (int)fx, y0 = (int)fy;
                float wx = ix - fx, wy = iy - fy;
                int x1 = min(x0 + 1, WW - 1);
                int y1 = min(y0 + 1, HH - 1);
                float a0 = __ldg(pc + y0 * WW + x0);
                float a1 = __ldg(pc + y0 * WW + x1);
                float a2 = __ldg(pc + y1 * WW + x0);
                float a3 = __ldg(pc + y1 * WW + x1);
                float h0 = fmaf(wx, a1 - a0, a0);
                float h1 = fmaf(wx, a3 - a2, a2);
                vv[s] = fmaf(wy, h1 - h0, h0);
            }
            float4 v4 = make_float4(vv[0], vv[1], vv[2], vv[3]);
            *reinterpret_cast<float4*>(oc + (size_t)(ohb + r) * OW + owb) = v4;
        }
    }
}

__global__ void __launch_bounds__(128, 5)
sample_kernel(const float* __restrict__ x, float* __restrict__ out) {
    __shared__ float4 sw4[8][128];       // (wx,wy) pairs, 16 KB

    int tid = threadIdx.x;
    int t = blockIdx.x * 128 + tid;      // 204800 threads
    int wp = t % 40;  int u = t / 40;
    int hp = u % 40;  u /= 40;
    int cchunk = u & 3;  u >>= 2;
    int gi = u & 3;
    int b  = u >> 2;

    int hbase = 2 * hp, wbase = 2 * wp;

    const float* offb = g_off + (size_t)b * OC * HW;

    bool valid = true;
#pragma unroll
    for (int r = 0; r < 4; r++) {
        int hprime = hbase + (r >> 1);
        int i = r & 1;
#pragma unroll
        for (int s = 0; s < 4; s++) {
            int wprime = wbase + (s >> 1);
            int j = s & 1;
            int k = gi * 4 + i * 2 + j;
            const float* op2 = offb + hprime * WW + wprime;
            float offx = __ldg(op2 + (size_t)k * HW);
            float offy = __ldg(op2 + (size_t)(16 + k) * HW);
            float px = (float)wprime + 0.25f * (offx + (float)(2 * j - 1));
            float py = (float)hprime + 0.25f * (offy + (float)(2 * i - 1));
            float ix = fminf(fmaxf(px, 0.0f), (float)(WW - 1));
            float iy = fminf(fmaxf(py, 0.0f), (float)(HH - 1));
            int tx0 = (s >> 1) + (s & 1);
            int ty0 = (r >> 1) + (r & 1);
            float wx = ix - (float)(wbase - 1 + tx0);
            float wy = iy - (float)(hbase - 1 + ty0);
            reinterpret_cast<float2*>(&sw4[r * 2 + (s >> 1)][tid])[s & 1] =
                make_float2(wx, wy);
            valid = valid && (wx >= 0.0f) && (wx <= 1.0f)
                          && (wy >= 0.0f) && (wy <= 1.0f);
        }
    }

    int c0 = cchunk * 16;
    const float* bp = x + (size_t)(b * CH + gi * 64 + c0) * HW;
    int ohb = 4 * hp;
    int owb = 4 * wp;
    float* opb = out + (size_t)(b * CH + gi * 64 + c0) * OHW;

    if (!valid) {
        sample_fallback(offb, bp, opb, gi, hbase, wbase, ohb, owb);
        return;
    }

    int rowo[4];
#pragma unroll
    for (int tq = 0; tq < 4; tq++)
        rowo[tq] = min(max(hbase - 1 + tq, 0), HH - 1) * WW;
    int colL = max(wbase - 1, 0);
    int colR = min(wbase + 2, WW - 1);

    const float* pc = bp;
    float* oc = opb + (size_t)ohb * OW + owb;

    float tvA[16], tvB[16];
    load_taps(tvA, pc, rowo, wbase, colL, colR);

#pragma unroll 1
    for (int c = 0; c < 16; c += 2) {
        load_taps(tvB, pc + HW, rowo, wbase, colL, colR);   // channel c+1
        comp_store(tvA, sw4, tid, oc);                      // channel c
        if (c + 2 < 16)
            load_taps(tvA, pc + 2 * HW, rowo, wbase, colL, colR); // c+2
        comp_store(tvB, sw4, tid, oc + OHW);                // channel c+1
        pc += 2 * HW;
        oc += 2 * OHW;
    }
}

extern "C" void kernel_launch(void* const* d_in, const int* in_sizes, int n_in,
                              void* d_out, int out_size) {
    const float* x    = (const float*)d_in[0];   // [8,256,80,80]
    const float* wq   = (const float*)d_in[1];   // [32,256,1,1]
    const float* bias = (const float*)d_in[2];   // [32]
    float* out = (float*)d_out;                  // [8,256,160,160]

    static bool attr_set = false;
    if (!attr_set) {
        cudaFuncSetAttribute(conv_off_kernel,
                             cudaFuncAttributeMaxDynamicSharedMemorySize,
                             CONV_SMEM);
        attr_set = true;
    }

    conv_off_kernel<<<400, 256, CONV_SMEM>>>(x, wq, bias);
    sample_kernel<<<1600, 128>>>(x, out);
}

// round 16
// speedup vs baseline: 1.1303x; 1.0171x over previous
#include <cuda_runtime.h>
#include <cstdint>

#define BATCH   8
#define CH      256
#define HH      80
#define WW      80
#define HW      (HH*WW)          // 6400
#define OC      32
#define GROUPS  4
#define OH      160
#define OW      160
#define OHW     (OH*OW)          // 25600

#define SC      32               // channels per conv stage
#define NSTAGE  (CH/SC)          // 8
#define CONV_SMEM (CH*OC*4 + 2*SC*32*16)   // 32KB ws + 32KB xs = 65536

typedef unsigned long long ull;

// scratch for conv output: 8*32*6400 floats = 6.55 MB
__device__ float g_off[BATCH * OC * HW];

__device__ __forceinline__ ull pack2(float a, float b) {
    ull r;
    asm("mov.b64 %0, {%1, %2};" : "=l"(r) : "f"(a), "f"(b));
    return r;
}

__device__ __forceinline__ ull ffma2(ull a, ull b, ull c) {
    ull d;
    asm("fma.rn.f32x2 %0, %1, %2, %3;" : "=l"(d) : "l"(a), "l"(b), "l"(c));
    return d;
}

__device__ __forceinline__ float lo_f(ull v) { return __uint_as_float((unsigned)(v & 0xffffffffULL)); }
__device__ __forceinline__ float hi_f(ull v) { return __uint_as_float((unsigned)(v >> 32)); }

// ---------------------------------------------------------------------------
// Kernel 1 (v6.2 — proven 26.8us, unchanged): 1x1 conv, smem-staged x.
// SC=32 double-buffered stages (8 stages, 16 barriers), 64KB dynamic smem.
// Block = 256 thr = 8 warps sharing the SAME 32 float4 positions; warp og
// owns oc [4og,4og+4) as two oc-pairs (broadcast LDS.128 -> pre-packed w).
// ---------------------------------------------------------------------------
__global__ void __launch_bounds__(256)
conv_off_kernel(const float* __restrict__ x,
                const float* __restrict__ wq,
                const float* __restrict__ bias) {
    extern __shared__ float smdyn[];
    float*  ws = smdyn;                                   // [c][o], 32 KB
    float4* xs = reinterpret_cast<float4*>(smdyn + CH * OC);  // [2][SC][32]

    int tid = threadIdx.x;
    for (int idx = tid; idx < CH * OC; idx += 256) {
        int o = idx >> 8;                   // coalesced over c
        int c = idx & 255;
        ws[c * OC + o] = __ldg(&wq[o * CH + c]);
    }

    int b   = blockIdx.x / 50;              // 400 blocks = 8 b x 50
    int qq0 = (blockIdx.x % 50) * 32;       // float4 base within channel
    const float4* xb = reinterpret_cast<const float4*>(x + (size_t)b * CH * HW);

    int c_l0 = tid >> 5;                    // 0..7
    int q0   = tid & 31;

    // prologue: stage 0 (channels 0..31), 4 rows per thread
    float4 r[4];
#pragma unroll
    for (int k = 0; k < 4; k++)
        r[k] = __ldg(&xb[(size_t)(c_l0 + 8 * k) * (HW / 4) + qq0 + q0]);
#pragma unroll
    for (int k = 0; k < 4; k++)
        xs[(c_l0 + 8 * k) * 32 + q0] = r[k];
    __syncthreads();                        // covers ws fill + stage 0

    int lane = tid & 31;
    int og   = tid >> 5;                    // 4 oc (2 oc-pairs) per warp
    const float* wso = ws + og * 4;

    ull acc[4][2];
#pragma unroll
    for (int i = 0; i < 4; i++) { acc[i][0] = 0ULL; acc[i][1] = 0ULL; }

#pragma unroll 1
    for (int st = 0; st < NSTAGE; st++) {
        int cb  = st * SC;
        int buf = st & 1;

        if (st + 1 < NSTAGE) {
#pragma unroll
            for (int k = 0; k < 4; k++)
                r[k] = __ldg(&xb[(size_t)(cb + SC + c_l0 + 8 * k) * (HW / 4) + qq0 + q0]);
        }

        const float4* xsb = xs + buf * SC * 32;
#pragma unroll
        for (int cl = 0; cl < SC; cl++) {
            float4 xv = xsb[cl * 32 + lane];                     // LDS.128
            ulonglong2 wp = *reinterpret_cast<const ulonglong2*>(
                wso + (cb + cl) * OC);                           // bcast LDS.128
            ull px0 = pack2(xv.x, xv.x);
            ull px1 = pack2(xv.y, xv.y);
            ull px2 = pack2(xv.z, xv.z);
            ull px3 = pack2(xv.w, xv.w);
            acc[0][0] = ffma2(px0, wp.x, acc[0][0]);
            acc[0][1] = ffma2(px0, wp.y, acc[0][1]);
            acc[1][0] = ffma2(px1, wp.x, acc[1][0]);
            acc[1][1] = ffma2(px1, wp.y, acc[1][1]);
            acc[2][0] = ffma2(px2, wp.x, acc[2][0]);
            acc[2][1] = ffma2(px2, wp.y, acc[2][1]);
            acc[3][0] = ffma2(px3, wp.x, acc[3][0]);
            acc[3][1] = ffma2(px3, wp.y, acc[3][1]);
        }

        __syncthreads();                    // done reading buf
        if (st + 1 < NSTAGE) {
            float4* xsn = xs + (buf ^ 1) * SC * 32;
#pragma unroll
            for (int k = 0; k < 4; k++)
                xsn[(c_l0 + 8 * k) * 32 + q0] = r[k];
            __syncthreads();                // next buffer ready
        }
    }

    float4* offp = reinterpret_cast<float4*>(g_off + (size_t)b * OC * HW);
#pragma unroll
    for (int p = 0; p < 2; p++) {
#pragma unroll
        for (int e = 0; e < 2; e++) {
            int oc = og * 4 + 2 * p + e;
            float bo = __ldg(&bias[oc]);
            float4 v;
            v.x = (e ? hi_f(acc[0][p]) : lo_f(acc[0][p])) + bo;
            v.y = (e ? hi_f(acc[1][p]) : lo_f(acc[1][p])) + bo;
            v.z = (e ? hi_f(acc[2][p]) : lo_f(acc[2][p])) + bo;
            v.w = (e ? hi_f(acc[3][p]) : lo_f(acc[3][p])) + bo;
            offp[(size_t)oc * (HW / 4) + qq0 + lane] = v;
        }
    }
}

// ---------------------------------------------------------------------------
// Kernel 2 (v8 — reverted verbatim, proven 49.7us): tiled bilinear sampling.
// Thread = (b, gi, 2x2 input pixels, 16-ch chunk) -> 4x4 outputs/channel from
// 16 static taps (12 loads: LDG.32 + LDG.64 + LDG.32 per clamped row).
// Weights (wx,wy) packed two-outputs-per-float4 in smem.
// ---------------------------------------------------------------------------
__device__ __noinline__ void sample_fallback(
    const float* __restrict__ offb, const float* __restrict__ bp,
    float* __restrict__ opb, int gi, int hbase, int wbase, int ohb, int owb)
{
    for (int c = 0; c < 16; c++) {
        const float* pc = bp + (size_t)c * HW;
        float* oc = opb + (size_t)c * OHW;
        for (int r = 0; r < 4; r++) {
            float vv[4];
            for (int s = 0; s < 4; s++) {
                int hprime = hbase + (r >> 1);
                int i = r & 1;
                int wprime = wbase + (s >> 1);
                int j = s & 1;
                int k = gi * 4 + i * 2 + j;
                const float* op2 = offb + hprime * WW + wprime;
                float offx = __ldg(op2 + (size_t)k * HW);
                float offy = __ldg(op2 + (size_t)(16 + k) * HW);
                float px = (float)wprime + 0.25f * (offx + (float)(2 * j - 1));
                float py = (float)hprime + 0.25f * (offy + (float)(2 * i - 1));
                float ix = fminf(fmaxf(px, 0.0f), (float)(WW - 1));
                float iy = fminf(fmaxf(py, 0.0f), (float)(HH - 1));
                float fx = floorf(ix), fy = floorf(iy);
                int x0 = (int)fx, y0 = (int)fy;
                float wx = ix - fx, wy = iy - fy;
                int x1 = min(x0 + 1, WW - 1);
                int y1 = min(y0 + 1, HH - 1);
                float a0 = __ldg(pc + y0 * WW + x0);
                float a1 = __ldg(pc + y0 * WW + x1);
                float a2 = __ldg(pc + y1 * WW + x0);
                float a3 = __ldg(pc + y1 * WW + x1);
                float h0 = fmaf(wx, a1 - a0, a0);
                float h1 = fmaf(wx, a3 - a2, a2);
                vv[s] = fmaf(wy, h1 - h0, h0);
            }
            float4 v4 = make_float4(vv[0], vv[1], vv[2], vv[3]);
            *reinterpret_cast<float4*>(oc + (size_t)(ohb + r) * OW + owb) = v4;
        }
    }
}

__global__ void __launch_bounds__(128, 6)
sample_kernel(const float* __restrict__ x, float* __restrict__ out) {
    // [r*2 + s/2][tid] = (wx_s, wy_s, wx_{s+1}, wy_{s+1}); 16 KB
    __shared__ float4 sw4[8][128];

    int tid = threadIdx.x;
    int t = blockIdx.x * 128 + tid;      // 204800 threads
    int wp = t % 40;  int u = t / 40;
    int hp = u % 40;  u /= 40;
    int cchunk = u & 3;  u >>= 2;
    int gi = u & 3;
    int b  = u >> 2;

    int hbase = 2 * hp, wbase = 2 * wp;

    const float* offb = g_off + (size_t)b * OC * HW;

    bool valid = true;
#pragma unroll
    for (int r = 0; r < 4; r++) {
        int hprime = hbase + (r >> 1);
        int i = r & 1;
#pragma unroll
        for (int s = 0; s < 4; s++) {
            int wprime = wbase + (s >> 1);
            int j = s & 1;
            int k = gi * 4 + i * 2 + j;
            const float* op2 = offb + hprime * WW + wprime;
            float offx = __ldg(op2 + (size_t)k * HW);
            float offy = __ldg(op2 + (size_t)(16 + k) * HW);
            float px = (float)wprime + 0.25f * (offx + (float)(2 * j - 1));
            float py = (float)hprime + 0.25f * (offy + (float)(2 * i - 1));
            float ix = fminf(fmaxf(px, 0.0f), (float)(WW - 1));
            float iy = fminf(fmaxf(py, 0.0f), (float)(HH - 1));
            int tx0 = (s >> 1) + (s & 1);
            int ty0 = (r >> 1) + (r & 1);
            float wx = ix - (float)(wbase - 1 + tx0);
            float wy = iy - (float)(hbase - 1 + ty0);
            reinterpret_cast<float2*>(&sw4[r * 2 + (s >> 1)][tid])[s & 1] =
                make_float2(wx, wy);
            valid = valid && (wx >= 0.0f) && (wx <= 1.0f)
                          && (wy >= 0.0f) && (wy <= 1.0f);
        }
    }

    int c0 = cchunk * 16;
    const float* bp = x + (size_t)(b * CH + gi * 64 + c0) * HW;
    int ohb = 4 * hp;
    int owb = 4 * wp;
    float* opb = out + (size_t)(b * CH + gi * 64 + c0) * OHW;

    if (!valid) {
        sample_fallback(offb, bp, opb, gi, hbase, wbase, ohb, owb);
        return;
    }

    int rowo[4];
#pragma unroll
    for (int tq = 0; tq < 4; tq++)
        rowo[tq] = min(max(hbase - 1 + tq, 0), HH - 1) * WW;
    int colL = max(wbase - 1, 0);
    int colR = min(wbase + 2, WW - 1);

#pragma unroll 1
    for (int c = 0; c < 16; c++) {
        const float* pc = bp + (size_t)c * HW;
        float tv[16];
#pragma unroll
        for (int ty = 0; ty < 4; ty++) {
            const float* rowp = pc + rowo[ty];
            tv[ty * 4 + 0] = __ldg(rowp + colL);
            float2 mid = __ldg(reinterpret_cast<const float2*>(rowp + wbase));
            tv[ty * 4 + 1] = mid.x;
            tv[ty * 4 + 2] = mid.y;
            tv[ty * 4 + 3] = __ldg(rowp + colR);
        }

        float* oc = opb + (size_t)c * OHW;
#pragma unroll
        for (int r = 0; r < 4; r++) {
            float4 wA = sw4[r * 2 + 0][tid];   // outputs s=0,1
            float4 wB = sw4[r * 2 + 1][tid];   // outputs s=2,3
            float vv[4];
#pragma unroll
            for (int sp = 0; sp < 2; sp++) {
                float4 wp4 = (sp == 0) ? wA : wB;
#pragma unroll
                for (int e = 0; e < 2; e++) {
                    int s = sp * 2 + e;
                    const int tx0 = (s >> 1) + (s & 1);
                    const int ty0 = (r >> 1) + (r & 1);
                    float wx = e ? wp4.z : wp4.x;
                    float wy = e ? wp4.w : wp4.y;
                    float a0 = tv[ty0 * 4 + tx0];
                    float a1 = tv[ty0 * 4 + tx0 + 1];
                    float a2 = tv[(ty0 + 1) * 4 + tx0];
                    float a3 = tv[(ty0 + 1) * 4 + tx0 + 1];
                    float h0 = fmaf(wx, a1 - a0, a0);
                    float h1 = fmaf(wx, a3 - a2, a2);
                    vv[s] = fmaf(wy, h1 - h0, h0);
                }
            }
            float4 v4 = make_float4(vv[0], vv[1], vv[2], vv[3]);
            *reinterpret_cast<float4*>(oc + (size_t)(ohb + r) * OW + owb) = v4;
        }
    }
}

extern "C" void kernel_launch(void* const* d_in, const int* in_sizes, int n_in,
                              void* d_out, int out_size) {
    const float* x    = (const float*)d_in[0];   // [8,256,80,80]
    const float* wq   = (const float*)d_in[1];   // [32,256,1,1]
    const float* bias = (const float*)d_in[2];   // [32]
    float* out = (float*)d_out;                  // [8,256,160,160]

    static bool attr_set = false;
    if (!attr_set) {
        cudaFuncSetAttribute(conv_off_kernel,
                             cudaFuncAttributeMaxDynamicSharedMemorySize,
                             CONV_SMEM);
        attr_set = true;
    }

    conv_off_kernel<<<400, 256, CONV_SMEM>>>(x, wq, bias);
    sample_kernel<<<1600, 128>>>(x, out);
}